// round 11
// baseline (speedup 1.0000x reference)
#include <cuda_runtime.h>

typedef unsigned long long u64;

// ---------------- packed f32x2 helpers (Blackwell FFMA2) ----------------
__device__ __forceinline__ u64 pack2(float a, float b) {
    u64 r; asm("mov.b64 %0, {%1, %2};" : "=l"(r) : "f"(a), "f"(b)); return r;
}
__device__ __forceinline__ u64 pack1(float a) { return pack2(a, a); }
__device__ __forceinline__ void unpack2(u64 v, float& a, float& b) {
    asm("mov.b64 {%0, %1}, %2;" : "=f"(a), "=f"(b) : "l"(v));
}
__device__ __forceinline__ u64 fma2(u64 a, u64 b, u64 c) {
    u64 d; asm("fma.rn.f32x2 %0, %1, %2, %3;" : "=l"(d) : "l"(a), "l"(b), "l"(c));
    return d;
}
__device__ __forceinline__ u64 relu2(u64 v) {
    float a, b; unpack2(v, a, b);
    a = fmaxf(a, 0.0f); b = fmaxf(b, 0.0f);
    return pack2(a, b);
}

// ---------------- constants ----------------
#define NTHREADS 128
#define ROWS_PER_THREAD 4
#define PAIRS 2
static constexpr int BATCH = 2097152;
static constexpr int CHUNK = BATCH / ROWS_PER_THREAD;  // 524288

// ---------------- shared weight table (u64 indices), raw, bias embedded --
// W0: 5 rows stride 10 [w0..w7, b, pad]    [0,50)
// W1..W4: 5 rows stride 6 [w0..w4, b]      [50,80) [80,110) [110,140) [140,170)
// W5: 4 rows stride 6 [w0..w4, b]          [170,194)
#define OFF_W0   0
#define OFF_W1   50
#define OFF_W2   80
#define OFF_W3   110
#define OFF_W4   140
#define OFF_W5   170
#define W_TOTAL  194

// raw table entry t: a single LDG from the right source (no arithmetic)
__device__ __forceinline__ float table_entry(
    int t,
    const float* __restrict__ W0, const float* __restrict__ b0,
    const float* __restrict__ W1, const float* __restrict__ b1,
    const float* __restrict__ W2, const float* __restrict__ b2,
    const float* __restrict__ W3, const float* __restrict__ b3,
    const float* __restrict__ W4, const float* __restrict__ b4,
    const float* __restrict__ W5, const float* __restrict__ b5) {
    if (t < 50) {
        int o = t / 10, k = t % 10;
        return (k < 8) ? W0[o * 8 + k] : ((k == 8) ? b0[o] : 0.0f);
    } else if (t < 80) {
        int i = t - OFF_W1, o = i / 6, k = i % 6;
        return (k < 5) ? W1[o * 5 + k] : b1[o];
    } else if (t < 110) {
        int i = t - OFF_W2, o = i / 6, k = i % 6;
        return (k < 5) ? W2[o * 5 + k] : b2[o];
    } else if (t < 140) {
        int i = t - OFF_W3, o = i / 6, k = i % 6;
        return (k < 5) ? W3[o * 5 + k] : b3[o];
    } else if (t < 170) {
        int i = t - OFF_W4, o = i / 6, k = i % 6;
        return (k < 5) ? W4[o * 5 + k] : b4[o];
    } else {
        int i = t - OFF_W5, o = i / 6, k = i % 6;
        return (k < 5) ? W5[o * 5 + k] : b5[o];
    }
}

// one 5->5 stage applied to both pairs; 3 LDS.128 per neuron row
__device__ __forceinline__ void stage5x5(u64 a[PAIRS][5], const u64* sw, int woff) {
    u64 h[PAIRS][5];
#pragma unroll
    for (int o = 0; o < 5; o++) {
        ulonglong2 wa = *reinterpret_cast<const ulonglong2*>(sw + woff + o * 6);
        ulonglong2 wb = *reinterpret_cast<const ulonglong2*>(sw + woff + o * 6 + 2);
        ulonglong2 wc = *reinterpret_cast<const ulonglong2*>(sw + woff + o * 6 + 4);
#pragma unroll
        for (int p = 0; p < PAIRS; p++) {
            u64 acc = wc.y;  // bias
            acc = fma2(a[p][0], wa.x, acc);
            acc = fma2(a[p][1], wa.y, acc);
            acc = fma2(a[p][2], wb.x, acc);
            acc = fma2(a[p][3], wb.y, acc);
            acc = fma2(a[p][4], wc.x, acc);
            h[p][o] = relu2(acc);
        }
    }
#pragma unroll
    for (int p = 0; p < PAIRS; p++)
#pragma unroll
        for (int o = 0; o < 5; o++) a[p][o] = h[p][o];
}

// pack one pair's inputs and run layer0 (8->5, no relu) + layer1 (5->relu(5)).
// After this returns, the 4 source float4 are dead — keeps register peak low.
__device__ __forceinline__ void stage01_pair(u64 aout[5], const u64* sw,
                                             const float4& l0, const float4& h0,
                                             const float4& l1, const float4& h1) {
    u64 xv[8];
    xv[0] = pack2(l0.x, l1.x); xv[1] = pack2(l0.y, l1.y);
    xv[2] = pack2(l0.z, l1.z); xv[3] = pack2(l0.w, l1.w);
    xv[4] = pack2(h0.x, h1.x); xv[5] = pack2(h0.y, h1.y);
    xv[6] = pack2(h0.z, h1.z); xv[7] = pack2(h0.w, h1.w);

    // layer0: 8 -> 5, no relu
    u64 t0[5];
#pragma unroll
    for (int o = 0; o < 5; o++) {
        ulonglong2 wa = *reinterpret_cast<const ulonglong2*>(sw + OFF_W0 + o * 10);
        ulonglong2 wb = *reinterpret_cast<const ulonglong2*>(sw + OFF_W0 + o * 10 + 2);
        ulonglong2 wc = *reinterpret_cast<const ulonglong2*>(sw + OFF_W0 + o * 10 + 4);
        ulonglong2 wd = *reinterpret_cast<const ulonglong2*>(sw + OFF_W0 + o * 10 + 6);
        ulonglong2 we = *reinterpret_cast<const ulonglong2*>(sw + OFF_W0 + o * 10 + 8);
        u64 acc = we.x;  // bias
        acc = fma2(xv[0], wa.x, acc);
        acc = fma2(xv[1], wa.y, acc);
        acc = fma2(xv[2], wb.x, acc);
        acc = fma2(xv[3], wb.y, acc);
        acc = fma2(xv[4], wc.x, acc);
        acc = fma2(xv[5], wc.y, acc);
        acc = fma2(xv[6], wd.x, acc);
        acc = fma2(xv[7], wd.y, acc);
        t0[o] = acc;
    }

    // layer1: 5 -> relu(5)
#pragma unroll
    for (int o = 0; o < 5; o++) {
        ulonglong2 wa = *reinterpret_cast<const ulonglong2*>(sw + OFF_W1 + o * 6);
        ulonglong2 wb = *reinterpret_cast<const ulonglong2*>(sw + OFF_W1 + o * 6 + 2);
        ulonglong2 wc = *reinterpret_cast<const ulonglong2*>(sw + OFF_W1 + o * 6 + 4);
        u64 acc = wc.y;  // bias
        acc = fma2(t0[0], wa.x, acc);
        acc = fma2(t0[1], wa.y, acc);
        acc = fma2(t0[2], wb.x, acc);
        acc = fma2(t0[3], wb.y, acc);
        acc = fma2(t0[4], wc.x, acc);
        aout[o] = relu2(acc);
    }
}

__global__ __launch_bounds__(NTHREADS, 8) void mlp_kernel(
    const float4* __restrict__ x, float4* __restrict__ out,
    const float* __restrict__ W0, const float* __restrict__ b0,
    const float* __restrict__ W1, const float* __restrict__ b1,
    const float* __restrict__ W2, const float* __restrict__ b2,
    const float* __restrict__ W3, const float* __restrict__ b3,
    const float* __restrict__ W4, const float* __restrict__ b4,
    const float* __restrict__ W5, const float* __restrict__ b5) {
    __shared__ __align__(16) u64 sw[W_TOTAL];
    const int t = threadIdx.x;
    const int idx = blockIdx.x * NTHREADS + t;  // 0..CHUNK-1
    const float4* xp = x + 2u * (unsigned)idx;

    // front-batch all 8 input vectors (4 rows x 2 float4) — max MLP
    float4 xl[ROWS_PER_THREAD], xh[ROWS_PER_THREAD];
#pragma unroll
    for (int r = 0; r < ROWS_PER_THREAD; r++) {
        const float4* xr = xp + (size_t)r * (2 * CHUNK);
        xl[r] = __ldg(xr);
        xh[r] = __ldg(xr + 1);
    }

    // raw weight table: <=2 predicated LDG+STS per thread
    if (t < W_TOTAL)
        sw[t] = pack1(table_entry(t, W0, b0, W1, b1, W2, b2, W3, b3, W4, b4, W5, b5));
    {
        int t2 = t + NTHREADS;
        if (t2 < W_TOTAL)
            sw[t2] = pack1(table_entry(t2, W0, b0, W1, b1, W2, b2, W3, b3, W4, b4, W5, b5));
    }
    __syncthreads();

    // ---- stages 0+1: pack + process one pair at a time (register peak) ----
    u64 a[PAIRS][5];
    stage01_pair(a[0], sw, xl[0], xh[0], xl[1], xh[1]);
    stage01_pair(a[1], sw, xl[2], xh[2], xl[3], xh[3]);

    // ---- layers 2..4: 5 -> relu(5), pair-amortized weights ----
    stage5x5(a, sw, OFF_W2);
    stage5x5(a, sw, OFF_W3);
    stage5x5(a, sw, OFF_W4);

    // ---- layer5: 5 -> relu(4) + streaming store ----
    float res[ROWS_PER_THREAD][4];
#pragma unroll
    for (int o = 0; o < 4; o++) {
        ulonglong2 wa = *reinterpret_cast<const ulonglong2*>(sw + OFF_W5 + o * 6);
        ulonglong2 wb = *reinterpret_cast<const ulonglong2*>(sw + OFF_W5 + o * 6 + 2);
        ulonglong2 wc = *reinterpret_cast<const ulonglong2*>(sw + OFF_W5 + o * 6 + 4);
#pragma unroll
        for (int p = 0; p < PAIRS; p++) {
            u64 acc = wc.y;  // bias
            acc = fma2(a[p][0], wa.x, acc);
            acc = fma2(a[p][1], wa.y, acc);
            acc = fma2(a[p][2], wb.x, acc);
            acc = fma2(a[p][3], wb.y, acc);
            acc = fma2(a[p][4], wc.x, acc);
            acc = relu2(acc);
            unpack2(acc, res[2 * p][o], res[2 * p + 1][o]);
        }
    }
    float4* op = out + idx;
#pragma unroll
    for (int r = 0; r < ROWS_PER_THREAD; r++) {
        __stcs(op + (size_t)r * CHUNK,
               make_float4(res[r][0], res[r][1], res[r][2], res[r][3]));
    }
}

extern "C" void kernel_launch(void* const* d_in, const int* in_sizes, int n_in,
                              void* d_out, int out_size) {
    const float* x  = (const float*)d_in[0];
    const float* W0 = (const float*)d_in[1];
    const float* b0 = (const float*)d_in[2];
    const float* W1 = (const float*)d_in[3];
    const float* b1 = (const float*)d_in[4];
    const float* W2 = (const float*)d_in[5];
    const float* b2 = (const float*)d_in[6];
    const float* W3 = (const float*)d_in[7];
    const float* b3 = (const float*)d_in[8];
    const float* W4 = (const float*)d_in[9];
    const float* b4 = (const float*)d_in[10];
    const float* W5 = (const float*)d_in[11];
    const float* b5 = (const float*)d_in[12];

    const int grid = (BATCH / ROWS_PER_THREAD) / NTHREADS;  // 4096
    mlp_kernel<<<grid, NTHREADS>>>((const float4*)x, (float4*)d_out,
                                   W0, b0, W1, b1, W2, b2, W3, b3, W4, b4, W5, b5);
}

// round 13
// speedup vs baseline: 4.4362x; 4.4362x over previous
#include <cuda_runtime.h>

typedef unsigned long long u64;

// ---------------- packed f32x2 helpers (Blackwell FFMA2) ----------------
__device__ __forceinline__ u64 pack2(float a, float b) {
    u64 r; asm("mov.b64 %0, {%1, %2};" : "=l"(r) : "f"(a), "f"(b)); return r;
}
__device__ __forceinline__ u64 pack1(float a) { return pack2(a, a); }
__device__ __forceinline__ void unpack2(u64 v, float& a, float& b) {
    asm("mov.b64 {%0, %1}, %2;" : "=f"(a), "=f"(b) : "l"(v));
}
__device__ __forceinline__ u64 fma2(u64 a, u64 b, u64 c) {
    u64 d; asm("fma.rn.f32x2 %0, %1, %2, %3;" : "=l"(d) : "l"(a), "l"(b), "l"(c));
    return d;
}
__device__ __forceinline__ u64 relu2(u64 v) {
    float a, b; unpack2(v, a, b);
    a = fmaxf(a, 0.0f); b = fmaxf(b, 0.0f);
    return pack2(a, b);
}

// ---------------- constants ----------------
#define NTHREADS 128
#define ROWS_PER_THREAD 4
#define PAIRS 2
static constexpr int BATCH = 2097152;
static constexpr int CHUNK = BATCH / ROWS_PER_THREAD;  // 524288

// ---------------- power-of-2 padded weight table (u64 indices) -----------
// stage1 fused: 5 rows, stride 16: [w0..w7, b, pad...]   [0,80)
// W2..W4:       5 rows, stride 8:  [w0..w4, b, pad, pad] [80,120) [120,160) [160,200)
// W5:           4 rows, stride 8:  [w0..w4, b, pad, pad] [200,232)
#define OFF_FW   0
#define OFF_W2   80
#define OFF_W3   120
#define OFF_W4   160
#define OFF_W5   200
#define W_TOTAL  232

// fused/padded table entry t from raw weights; all index math is shift/mask
__device__ __forceinline__ float table_entry(
    int t,
    const float* __restrict__ W0, const float* __restrict__ b0,
    const float* __restrict__ W1, const float* __restrict__ b1,
    const float* __restrict__ W2, const float* __restrict__ b2,
    const float* __restrict__ W3, const float* __restrict__ b3,
    const float* __restrict__ W4, const float* __restrict__ b4,
    const float* __restrict__ W5, const float* __restrict__ b5) {
    if (t < 80) {
        int o = t >> 4, k = t & 15;
        if (k < 8) {
            // fused W01[o][k] = sum_h W1[o][h] * W0[h][k]
            float s = 0.0f;
#pragma unroll
            for (int h = 0; h < 5; h++) s += W1[o * 5 + h] * W0[h * 8 + k];
            return s;
        } else if (k == 8) {
            // fused b01[o] = b1[o] + sum_h W1[o][h] * b0[h]
            float s = b1[o];
#pragma unroll
            for (int h = 0; h < 5; h++) s += W1[o * 5 + h] * b0[h];
            return s;
        }
        return 0.0f;
    }
    int i = t - 80;            // 0..151
    int st = i >> 5;           // 0..4 : half-stage index (2 rows per 16)
    int o = (i >> 3) & 3;      // row within 2-row group... recompute properly:
    // simpler exact mapping: stage block = (t - 80) / 40, within = (t - 80) % 40
    int blk = i / 40;          // 0:W2 1:W3 2:W4 3:W5   (const-div -> mul/shift)
    int w = i - blk * 40;      // 0..39
    int row = w >> 3, k = w & 7;
    (void)st; (void)o;
    const float* Wt; const float* bt; int nrows;
    if (blk == 0)      { Wt = W2; bt = b2; nrows = 5; }
    else if (blk == 1) { Wt = W3; bt = b3; nrows = 5; }
    else if (blk == 2) { Wt = W4; bt = b4; nrows = 5; }
    else               { Wt = W5; bt = b5; nrows = 4; }
    if (row >= nrows) return 0.0f;
    if (k < 5) return Wt[row * 5 + k];
    if (k == 5) return bt[row];
    return 0.0f;
}

// one hidden stage (5 -> relu(5)): 3x LDS.128 per neuron row (w0..w4, bias),
// each row applied to both pairs
__device__ __forceinline__ void hidden_stage(u64 a[PAIRS][5], const u64* sw, int woff) {
    u64 h[PAIRS][5];
#pragma unroll
    for (int o = 0; o < 5; o++) {
        ulonglong2 wa = *reinterpret_cast<const ulonglong2*>(sw + woff + o * 8);
        ulonglong2 wb = *reinterpret_cast<const ulonglong2*>(sw + woff + o * 8 + 2);
        ulonglong2 wc = *reinterpret_cast<const ulonglong2*>(sw + woff + o * 8 + 4);  // (w4, bias)
#pragma unroll
        for (int p = 0; p < PAIRS; p++) {
            u64 acc = wc.y;  // bias
            acc = fma2(a[p][0], wa.x, acc);
            acc = fma2(a[p][1], wa.y, acc);
            acc = fma2(a[p][2], wb.x, acc);
            acc = fma2(a[p][3], wb.y, acc);
            acc = fma2(a[p][4], wc.x, acc);
            h[p][o] = relu2(acc);
        }
    }
#pragma unroll
    for (int p = 0; p < PAIRS; p++)
#pragma unroll
        for (int o = 0; o < 5; o++) a[p][o] = h[p][o];
}

__global__ __launch_bounds__(NTHREADS, 8) void mlp_kernel(
    const float4* __restrict__ x, float4* __restrict__ out,
    const float* __restrict__ W0, const float* __restrict__ b0,
    const float* __restrict__ W1, const float* __restrict__ b1,
    const float* __restrict__ W2, const float* __restrict__ b2,
    const float* __restrict__ W3, const float* __restrict__ b3,
    const float* __restrict__ W4, const float* __restrict__ b4,
    const float* __restrict__ W5, const float* __restrict__ b5) {
    __shared__ __align__(16) u64 sw[W_TOTAL];
    const int t = threadIdx.x;
    const int idx = blockIdx.x * NTHREADS + t;  // 0..CHUNK-1
    const float4* xp = x + 2u * (unsigned)idx;

    // weight gather + table build FIRST so its LDGs batch ahead of input LDGs
    {
        float v0 = table_entry(t, W0, b0, W1, b1, W2, b2, W3, b3, W4, b4, W5, b5);
        sw[t] = pack1(v0);
        int t2 = t + NTHREADS;
        if (t2 < W_TOTAL) {
            float v1 = table_entry(t2, W0, b0, W1, b1, W2, b2, W3, b3, W4, b4, W5, b5);
            sw[t2] = pack1(v1);
        }
    }

    // front-batch input loads (independent of the weight table)
    float4 xr0[ROWS_PER_THREAD], xr1[ROWS_PER_THREAD];
#pragma unroll
    for (int r = 0; r < ROWS_PER_THREAD; r++) {
        const float4* xr = xp + (size_t)r * (2 * CHUNK);
        xr0[r] = __ldg(xr);
        xr1[r] = __ldg(xr + 1);
    }
    __syncthreads();

    // ---- stage 1: fused layer01 (8 -> relu(5)) ----
    u64 a[PAIRS][5];
#pragma unroll
    for (int o = 0; o < 5; o++) {
        ulonglong2 wa = *reinterpret_cast<const ulonglong2*>(sw + OFF_FW + o * 16);
        ulonglong2 wb = *reinterpret_cast<const ulonglong2*>(sw + OFF_FW + o * 16 + 2);
        ulonglong2 wc = *reinterpret_cast<const ulonglong2*>(sw + OFF_FW + o * 16 + 4);
        ulonglong2 wd = *reinterpret_cast<const ulonglong2*>(sw + OFF_FW + o * 16 + 6);
        u64 bb = sw[OFF_FW + o * 16 + 8];
#pragma unroll
        for (int p = 0; p < PAIRS; p++) {
            const int ra = 2 * p, rb = 2 * p + 1;
            u64 acc = bb;  // bias
            acc = fma2(pack2(xr0[ra].x, xr0[rb].x), wa.x, acc);
            acc = fma2(pack2(xr0[ra].y, xr0[rb].y), wa.y, acc);
            acc = fma2(pack2(xr0[ra].z, xr0[rb].z), wb.x, acc);
            acc = fma2(pack2(xr0[ra].w, xr0[rb].w), wb.y, acc);
            acc = fma2(pack2(xr1[ra].x, xr1[rb].x), wc.x, acc);
            acc = fma2(pack2(xr1[ra].y, xr1[rb].y), wc.y, acc);
            acc = fma2(pack2(xr1[ra].z, xr1[rb].z), wd.x, acc);
            acc = fma2(pack2(xr1[ra].w, xr1[rb].w), wd.y, acc);
            a[p][o] = relu2(acc);
        }
    }

    // ---- stages 2..4: hidden layers ----
    hidden_stage(a, sw, OFF_W2);
    hidden_stage(a, sw, OFF_W3);
    hidden_stage(a, sw, OFF_W4);

    // ---- stage 5: output layer (5 -> relu(4)) + streaming store ----
    float res[ROWS_PER_THREAD][4];
#pragma unroll
    for (int o = 0; o < 4; o++) {
        ulonglong2 wa = *reinterpret_cast<const ulonglong2*>(sw + OFF_W5 + o * 8);
        ulonglong2 wb = *reinterpret_cast<const ulonglong2*>(sw + OFF_W5 + o * 8 + 2);
        ulonglong2 wc = *reinterpret_cast<const ulonglong2*>(sw + OFF_W5 + o * 8 + 4);  // (w4, bias)
#pragma unroll
        for (int p = 0; p < PAIRS; p++) {
            u64 acc = wc.y;  // bias
            acc = fma2(a[p][0], wa.x, acc);
            acc = fma2(a[p][1], wa.y, acc);
            acc = fma2(a[p][2], wb.x, acc);
            acc = fma2(a[p][3], wb.y, acc);
            acc = fma2(a[p][4], wc.x, acc);
            acc = relu2(acc);
            unpack2(acc, res[2 * p][o], res[2 * p + 1][o]);
        }
    }
    float4* op = out + idx;
#pragma unroll
    for (int r = 0; r < ROWS_PER_THREAD; r++) {
        __stcs(op + (size_t)r * CHUNK,
               make_float4(res[r][0], res[r][1], res[r][2], res[r][3]));
    }
}

extern "C" void kernel_launch(void* const* d_in, const int* in_sizes, int n_in,
                              void* d_out, int out_size) {
    const float* x  = (const float*)d_in[0];
    const float* W0 = (const float*)d_in[1];
    const float* b0 = (const float*)d_in[2];
    const float* W1 = (const float*)d_in[3];
    const float* b1 = (const float*)d_in[4];
    const float* W2 = (const float*)d_in[5];
    const float* b2 = (const float*)d_in[6];
    const float* W3 = (const float*)d_in[7];
    const float* b3 = (const float*)d_in[8];
    const float* W4 = (const float*)d_in[9];
    const float* b4 = (const float*)d_in[10];
    const float* W5 = (const float*)d_in[11];
    const float* b5 = (const float*)d_in[12];

    const int grid = (BATCH / ROWS_PER_THREAD) / NTHREADS;  // 4096
    mlp_kernel<<<grid, NTHREADS>>>((const float4*)x, (float4*)d_out,
                                   W0, b0, W1, b1, W2, b2, W3, b3, W4, b4, W5, b5);
}